// round 8
// baseline (speedup 1.0000x reference)
#include <cuda_runtime.h>
#include <cuda_bf16.h>
#include <cstdint>

// Round 8: scan rebuilt as 512-thread split-K (each thread: 2 cols x 2 rows x
// half the k range; partials exchanged via smem; epilogue split by batch row).
// HMMA bf16 split GEMM for pre = x@W^T unchanged from round 7.

#define BB 256
#define SS 2048
#define II 64
#define HH 128
#define GG 512
#define NCTA 128
#define NTHR 512

// scan per-thread weight split (of its 64-row k-half)
#define RK 40                    // reg rows (20 u64 pairs per col)
#define SK 24                    // smem rows (12 float4 chunks)
#define SW4_CHUNKS 12
#define SW4_FLOATS (SW4_CHUNKS * NTHR * 4)
#define HB_FLOATS  (2 * 2 * HH)
#define PSUM_FLOATS (NTHR * 4)
#define SCAN_SMEM_BYTES ((SW4_FLOATS + HB_FLOATS + PSUM_FLOATS) * 4)

typedef unsigned long long u64;

__device__ float g_pre[(long long)BB * SS * GG];                 // 1 GB scratch
__device__ __align__(16) unsigned g_wh[GG * II / 2];
__device__ __align__(16) unsigned g_wl[GG * II / 2];

__device__ __forceinline__ u64 ffma2(u64 a, u64 b, u64 c) {
    u64 d;
    asm("fma.rn.f32x2 %0, %1, %2, %3;" : "=l"(d) : "l"(a), "l"(b), "l"(c));
    return d;
}
__device__ __forceinline__ u64 packf2(float lo, float hi) {
    u64 r;
    asm("mov.b64 %0, {%1, %2};" : "=l"(r) : "f"(lo), "f"(hi));
    return r;
}
__device__ __forceinline__ float2 unpackf2(u64 v) {
    float2 r;
    asm("mov.b64 {%0, %1}, %2;" : "=f"(r.x), "=f"(r.y) : "l"(v));
    return r;
}
__device__ __forceinline__ float fast_tanh(float x) {
    float xc = fminf(fmaxf(x, -12.0f), 12.0f);
    float e  = __expf(2.0f * xc);
    return __fdividef(e - 1.0f, e + 1.0f);
}
__device__ __forceinline__ unsigned pack_bf16_hi(float a, float b) {
    __nv_bfloat16 ah = __float2bfloat16(a), bh = __float2bfloat16(b);
    return (unsigned)__bfloat16_as_ushort(ah) | ((unsigned)__bfloat16_as_ushort(bh) << 16);
}
__device__ __forceinline__ unsigned pack_bf16_lo(float a, float b) {
    __nv_bfloat16 ah = __float2bfloat16(a), bh = __float2bfloat16(b);
    __nv_bfloat16 al = __float2bfloat16(a - __bfloat162float(ah));
    __nv_bfloat16 bl = __float2bfloat16(b - __bfloat162float(bh));
    return (unsigned)__bfloat16_as_ushort(al) | ((unsigned)__bfloat16_as_ushort(bl) << 16);
}
__device__ __forceinline__ void mma16816(float* c, const unsigned* a,
                                         unsigned b0, unsigned b1) {
    asm volatile(
        "mma.sync.aligned.m16n8k16.row.col.f32.bf16.bf16.f32 "
        "{%0,%1,%2,%3}, {%4,%5,%6,%7}, {%8,%9}, {%0,%1,%2,%3};"
        : "+f"(c[0]), "+f"(c[1]), "+f"(c[2]), "+f"(c[3])
        : "r"(a[0]), "r"(a[1]), "r"(a[2]), "r"(a[3]), "r"(b0), "r"(b1));
}

// ---------------------------------------------------------------------------
__global__ void prep_w_kernel(const float* __restrict__ Wm) {
    int i = blockIdx.x * 256 + threadIdx.x;
    float a = Wm[2 * i], b = Wm[2 * i + 1];
    g_wh[i] = pack_bf16_hi(a, b);
    g_wl[i] = pack_bf16_lo(a, b);
}

// ---------------------------------------------------------------------------
// HMMA GEMM (unchanged from round 7): CTA M=64 x N=512, K=64, 3-term bf16 split
// ---------------------------------------------------------------------------
#define ARS 36
#define OFF_AH 0
#define OFF_AL (64 * ARS)
#define OFF_BH (2 * 64 * ARS)
#define OFF_BL (OFF_BH + 512 * ARS)
#define GEMM_SMEM_UINTS (OFF_BL + 512 * ARS)
#define GEMM_SMEM_BYTES (GEMM_SMEM_UINTS * 4)

__global__ void __launch_bounds__(256, 1)
pre_gemm_mma(const float* __restrict__ xg, float* __restrict__ pre)
{
    extern __shared__ unsigned usm[];
    unsigned* Ah = usm + OFF_AH;
    unsigned* Al = usm + OFF_AL;
    unsigned* Bh = usm + OFF_BH;
    unsigned* Bl = usm + OFF_BL;

    const int tid = threadIdx.x;
    {
        const float* xt = xg + (long long)blockIdx.x * 64 * II;
#pragma unroll
        for (int j = 0; j < 8; j++) {
            int idx = tid + j * 256;
            int row = idx >> 5, kp = idx & 31;
            float2 v = *(const float2*)(xt + row * II + kp * 2);
            Ah[row * ARS + kp] = pack_bf16_hi(v.x, v.y);
            Al[row * ARS + kp] = pack_bf16_lo(v.x, v.y);
        }
    }
    {
#pragma unroll
        for (int j = 0; j < 16; j++) {
            int idx = tid + j * 256;
            int n = idx >> 3, kq = idx & 7;
            uint4 hv = ((const uint4*)g_wh)[idx];
            uint4 lv = ((const uint4*)g_wl)[idx];
            *(uint4*)(Bh + n * ARS + kq * 4) = hv;
            *(uint4*)(Bl + n * ARS + kq * 4) = lv;
        }
    }
    __syncthreads();

    const int w    = tid >> 5;
    const int lane = tid & 31;
    const int gid  = lane >> 2;
    const int tig  = lane & 3;
    const int mg   = w >> 2;
    const int ng   = w & 3;

    float acc[2][16][4];
#pragma unroll
    for (int mt = 0; mt < 2; mt++)
#pragma unroll
        for (int nc = 0; nc < 16; nc++)
#pragma unroll
            for (int e = 0; e < 4; e++) acc[mt][nc][e] = 0.0f;

#pragma unroll
    for (int ks = 0; ks < 4; ks++) {
        unsigned ah[2][4], al[2][4];
#pragma unroll
        for (int mt = 0; mt < 2; mt++) {
            int r0 = mg * 32 + mt * 16 + gid;
            int ui = ks * 8 + tig;
            ah[mt][0] = Ah[r0 * ARS + ui];
            ah[mt][1] = Ah[(r0 + 8) * ARS + ui];
            ah[mt][2] = Ah[r0 * ARS + ui + 4];
            ah[mt][3] = Ah[(r0 + 8) * ARS + ui + 4];
            al[mt][0] = Al[r0 * ARS + ui];
            al[mt][1] = Al[(r0 + 8) * ARS + ui];
            al[mt][2] = Al[r0 * ARS + ui + 4];
            al[mt][3] = Al[(r0 + 8) * ARS + ui + 4];
        }
#pragma unroll
        for (int nc = 0; nc < 16; nc++) {
            int n  = ng * 128 + nc * 8 + gid;
            int ui = ks * 8 + tig;
            unsigned bh0 = Bh[n * ARS + ui];
            unsigned bh1 = Bh[n * ARS + ui + 4];
            unsigned bl0 = Bl[n * ARS + ui];
            unsigned bl1 = Bl[n * ARS + ui + 4];
#pragma unroll
            for (int mt = 0; mt < 2; mt++) {
                mma16816(acc[mt][nc], ah[mt], bh0, bh1);
                mma16816(acc[mt][nc], al[mt], bh0, bh1);
                mma16816(acc[mt][nc], ah[mt], bl0, bl1);
            }
        }
    }
#pragma unroll
    for (int mt = 0; mt < 2; mt++) {
#pragma unroll
        for (int nc = 0; nc < 16; nc++) {
            long long m = (long long)blockIdx.x * 64 + mg * 32 + mt * 16 + gid;
            int n = ng * 128 + nc * 8 + tig * 2;
            *(float2*)(pre + m * GG + n)       = make_float2(acc[mt][nc][0], acc[mt][nc][1]);
            *(float2*)(pre + (m + 8) * GG + n) = make_float2(acc[mt][nc][2], acc[mt][nc][3]);
        }
    }
}

// ---------------------------------------------------------------------------
// scan: 512 threads, split-K. Thread t: half = t>>8 owns k in [64*half, +64),
// cols c0 = 16l + 2*(w&7), c1 = c0+1, both batch rows. Partials exchanged via
// psum smem; epilogue: half h updates the states of batch row h.
// ---------------------------------------------------------------------------
__global__ void __launch_bounds__(NTHR, 1)
slstm_scan_kernel(const float* __restrict__ pre, const float* __restrict__ Rm,
                  const float* __restrict__ bias, float* __restrict__ out)
{
    extern __shared__ float smem[];
    float4* sW4  = (float4*)smem;                       // [SW4_CHUNKS][NTHR]
    float*  hb   = smem + SW4_FLOATS;                   // [2][2][HH]
    float4* psum = (float4*)(smem + SW4_FLOATS + HB_FLOATS);  // [NTHR]

    const int t    = threadIdx.x;
    const int half = t >> 8;
    const int w8   = (t >> 5) & 7;
    const int l    = t & 31;
    const int c0   = 16 * l + 2 * w8;
    const int c1   = c0 + 1;
    const int b0   = blockIdx.x * 2;
    const int kb   = half * 64;                 // k-half base

    // ---- register weights: rows [kb, kb+RK) for c0/c1, pair-packed ----
    u64 wp0[RK / 2], wp1[RK / 2];
#pragma unroll
    for (int j = 0; j < RK / 2; j++) {
        int k = kb + 2 * j;
        wp0[j] = packf2(Rm[k * GG + c0], Rm[(k + 1) * GG + c0]);
        wp1[j] = packf2(Rm[k * GG + c1], Rm[(k + 1) * GG + c1]);
    }
    // ---- smem weights: rows [kb+RK, kb+64), chunk i = rows kb+RK+2i ----
#pragma unroll
    for (int i = 0; i < SW4_CHUNKS; i++) {
        int k = kb + RK + 2 * i;
        sW4[i * NTHR + t] = make_float4(Rm[k * GG + c0], Rm[(k + 1) * GG + c0],
                                        Rm[k * GG + c1], Rm[(k + 1) * GG + c1]);
    }
    const float bg0 = bias[c0];
    const float bg1 = bias[c1];

    if (t < HB_FLOATS) hb[t] = 0.0f;
    __syncthreads();

    // pre pointer for this thread's epilogue row (= half)
    const float* pr = pre + (long long)(b0 + half) * SS * GG;
    float2 p = __ldg((const float2*)(pr + c0));

    // epilogue mapping: lane -> (hid), duplicated over lane bit 4
    const int j7 = l & 7;
    const int bsel = (l >> 3) & 1;
    const int my_hid = 16 * j7 + 2 * w8 + bsel;
    float c_ = 0.0f, n_ = 0.0f, m_ = 0.0f;

#pragma unroll 1
    for (int step = 0; step < SS; step++) {
        const float* hbc = hb + (step & 1) * 256;
        const float* h0 = hbc + kb;             // row 0, this k-half
        const float* h1 = hbc + HH + kb;        // row 1
        float* hn = hb + ((step + 1) & 1) * 256;

        float2 q = make_float2(0.f, 0.f);
        if (step + 1 < SS)
            q = __ldg((const float2*)(pr + (long long)(step + 1) * GG + c0));

        u64 a00 = 0, a10 = 0, a01 = 0, a11 = 0;   // a{col}{row}

#pragma unroll
        for (int i = 0; i < RK / 4; i++) {        // reg rows, 4 per iter
            ulonglong2 hp0 = *(const ulonglong2*)(h0 + 4 * i);
            ulonglong2 hp1 = *(const ulonglong2*)(h1 + 4 * i);
            int j = 2 * i;
            a00 = ffma2(hp0.x, wp0[j],     a00);
            a10 = ffma2(hp0.x, wp1[j],     a10);
            a01 = ffma2(hp1.x, wp0[j],     a01);
            a11 = ffma2(hp1.x, wp1[j],     a11);
            a00 = ffma2(hp0.y, wp0[j + 1], a00);
            a10 = ffma2(hp0.y, wp1[j + 1], a10);
            a01 = ffma2(hp1.y, wp0[j + 1], a01);
            a11 = ffma2(hp1.y, wp1[j + 1], a11);
        }
#pragma unroll
        for (int i = 0; i < SK / 4; i++) {        // smem rows, 4 per iter
            ulonglong2 wA = *(const ulonglong2*)&sW4[(2 * i) * NTHR + t];
            ulonglong2 wB = *(const ulonglong2*)&sW4[(2 * i + 1) * NTHR + t];
            ulonglong2 hp0 = *(const ulonglong2*)(h0 + RK + 4 * i);
            ulonglong2 hp1 = *(const ulonglong2*)(h1 + RK + 4 * i);
            a00 = ffma2(hp0.x, wA.x, a00);
            a10 = ffma2(hp0.x, wA.y, a10);
            a01 = ffma2(hp1.x, wA.x, a01);
            a11 = ffma2(hp1.x, wA.y, a11);
            a00 = ffma2(hp0.y, wB.x, a00);
            a10 = ffma2(hp0.y, wB.y, a10);
            a01 = ffma2(hp1.y, wB.x, a01);
            a11 = ffma2(hp1.y, wB.y, a11);
        }

        float2 f00 = unpackf2(a00), f10 = unpackf2(a10);
        float2 f01 = unpackf2(a01), f11 = unpackf2(a11);
        psum[t] = make_float4(f00.x + f00.y, f10.x + f10.y,
                              f01.x + f01.y, f11.x + f11.y);
        __syncthreads();

        // combine with partner's partials; pick this half's batch row
        float4 pp = psum[t ^ 256];
        float4 ow = psum[t];
        float aa, bb;
        if (half == 0) {
            aa = ow.x + pp.x + p.x + bg0;    // gate(c0, row0)
            bb = ow.y + pp.y + p.y + bg1;    // gate(c1, row0)
        } else {
            aa = ow.z + pp.z + p.x + bg0;    // gate(c0, row1)
            bb = ow.w + pp.w + p.y + bg1;    // gate(c1, row1)
        }

        // gate gather: gate q' of hid(my) lives in lane (q'<<3)|j7, col b=bsel
        float s0a = __shfl_sync(0xFFFFFFFFu, aa, j7);
        float s0b = __shfl_sync(0xFFFFFFFFu, bb, j7);
        float s1a = __shfl_sync(0xFFFFFFFFu, aa, 8 | j7);
        float s1b = __shfl_sync(0xFFFFFFFFu, bb, 8 | j7);
        float s2a = __shfl_sync(0xFFFFFFFFu, aa, 16 | j7);
        float s2b = __shfl_sync(0xFFFFFFFFu, bb, 16 | j7);
        float s3a = __shfl_sync(0xFFFFFFFFu, aa, 24 | j7);
        float s3b = __shfl_sync(0xFFFFFFFFu, bb, 24 | j7);
        float iv = bsel ? s0b : s0a;
        float fv = bsel ? s1b : s1a;
        float ov = bsel ? s2b : s2a;
        float zv = bsel ? s3b : s3a;

        // exponential-gating state update for (row=half, my_hid); lanes l and
        // l+16 duplicate the computation, only l<16 stores.
        float tz = fast_tanh(zv);
        float so = __fdividef(1.0f, 1.0f + __expf(-ov));
        float lf = fminf(fv, 0.0f) - __logf(1.0f + __expf(-fabsf(fv)));
        float mn = fmaxf(lf + m_, iv);
        float ip = __expf(iv - mn);
        float fp = __expf(lf + m_ - mn);
        c_ = fp * c_ + ip * tz;
        n_ = fp * n_ + ip;
        m_ = mn;
        float hv = so * fast_tanh(__fdividef(c_, n_));

        if (l < 16) {
            hn[half * HH + my_hid] = hv;
            out[((long long)(b0 + half) * SS + step) * HH + my_hid] = hv;
        }
        p = q;
        __syncthreads();
    }
}

extern "C" void kernel_launch(void* const* d_in, const int* in_sizes, int n_in,
                              void* d_out, int out_size)
{
    const float* xg = (const float*)d_in[0];
    const float* Wm = (const float*)d_in[1];
    const float* Rm = (const float*)d_in[2];
    const float* bv = (const float*)d_in[3];
    if (n_in >= 3 && in_sizes[1] == HH * GG && in_sizes[2] == GG * II) {
        const float* t = Wm; Wm = Rm; Rm = t;
    }
    float* out = (float*)d_out;

    float* pre = nullptr;
    cudaGetSymbolAddress((void**)&pre, g_pre);

    cudaFuncSetAttribute(pre_gemm_mma,
                         cudaFuncAttributeMaxDynamicSharedMemorySize, GEMM_SMEM_BYTES);
    cudaFuncSetAttribute(slstm_scan_kernel,
                         cudaFuncAttributeMaxDynamicSharedMemorySize, SCAN_SMEM_BYTES);

    prep_w_kernel<<<GG * II / 2 / 256, 256>>>(Wm);
    pre_gemm_mma<<<(BB * SS) / 64, 256, GEMM_SMEM_BYTES>>>(xg, pre);
    slstm_scan_kernel<<<NCTA, NTHR, SCAN_SMEM_BYTES>>>(pre, Rm, bv, out);
}